// round 1
// baseline (speedup 1.0000x reference)
#include <cuda_runtime.h>
#include <math.h>

#define TPB 256
#define MAXK 128

// Scratch accumulators: [b*3+0]=stc_sum, [b*3+1]=str_sum, [b*3+2]=pos_count
__device__ float g_acc[16];

__global__ void zero_acc_kernel() {
    if (threadIdx.x < 16) g_acc[threadIdx.x] = 0.f;
}

__device__ __forceinline__ float softplusf(float z) {
    // log(1 + exp(z)), stable
    return fmaxf(z, 0.f) + log1pf(__expf(-fabsf(z)));
}

__global__ __launch_bounds__(TPB) void loss_kernel(
    const float* __restrict__ prop,     // (B, A, 6)
    const float* __restrict__ anchors,  // (A, 4) xywh
    const float* __restrict__ gt,       // (B, K, 4) xywh
    int A, int K)
{
    __shared__ float4 s_g[MAXK];   // gt boxes xyxy
    __shared__ float  s_ga[MAXK];  // gt areas
    __shared__ float  r0[8], r1[8], r2[8];

    const int b = blockIdx.y;

    for (int k = threadIdx.x; k < K; k += TPB) {
        const float* g = gt + ((size_t)b * K + k) * 4;
        float gx = g[0], gy = g[1], gw = g[2], gh = g[3];
        s_g[k]  = make_float4(gx, gy, gx + gw, gy + gh);
        s_ga[k] = gw * gh;
    }
    __syncthreads();

    const int a = blockIdx.x * TPB + threadIdx.x;
    float stc = 0.f, strl = 0.f, cnt = 0.f;

    if (a < A) {
        float4 an = reinterpret_cast<const float4*>(anchors)[a];
        const float ax1 = an.x, ay1 = an.y;
        const float ax2 = an.x + an.z, ay2 = an.y + an.w;
        const float areaA = an.z * an.w;

        // division-free argmax over K (denominators strictly positive)
        float bI = 0.f, bD = 1.f;
        int   bK = 0;
#pragma unroll 8
        for (int k = 0; k < K; k++) {
            float4 g = s_g[k];
            float w = fminf(ax2, g.z) - fmaxf(ax1, g.x);
            float h = fminf(ay2, g.w) - fmaxf(ay1, g.y);
            w = fmaxf(w, 0.f);
            h = fmaxf(h, 0.f);
            float inter = w * h;
            float denom = (areaA + s_ga[k]) - inter;
            // iou_k > iou_best  <=>  inter*bD > bI*denom  (strict: keep first max)
            if (inter * bD > bI * denom) { bI = inter; bD = denom; bK = k; }
        }
        const float ts = bI / bD;  // target_score = max IoU

        const float* p = prop + ((size_t)b * A + a) * 6;
        float2 p01 = *reinterpret_cast<const float2*>(p);
        float2 p23 = *reinterpret_cast<const float2*>(p + 2);
        const float x = p[4];  // logit
        const float sig = 1.f / (1.f + __expf(-x));

        if (ts >= 0.5f) {
            cnt = 1.f;
            // focal with t=1: alpha * softplus(-x) * (1-p)^2
            float om = 1.f - sig;
            stc = 0.25f * softplusf(-x) * om * om;
            // elementwise IoU(pred box, matched gt box)
            float4 g = s_g[bK];
            float px2 = p01.x + p23.x, py2 = p01.y + p23.y;
            float ew = fmaxf(fminf(px2, g.z) - fmaxf(p01.x, g.x), 0.f);
            float eh = fmaxf(fminf(py2, g.w) - fmaxf(p01.y, g.y), 0.f);
            float ei = ew * eh;
            float eiou = ei / ((p23.x * p23.y + s_ga[bK]) - ei);
            strl = -__logf(eiou + 0.01f);
        } else if (ts < 0.4f) {
            // focal with t=0: (1-alpha) * softplus(x) * p^2
            stc = 0.75f * softplusf(x) * sig * sig;
        }
    }

    // block reduction of (stc, strl, cnt)
    unsigned m = 0xFFFFFFFFu;
#pragma unroll
    for (int o = 16; o; o >>= 1) {
        stc  += __shfl_down_sync(m, stc,  o);
        strl += __shfl_down_sync(m, strl, o);
        cnt  += __shfl_down_sync(m, cnt,  o);
    }
    const int wid = threadIdx.x >> 5, lane = threadIdx.x & 31;
    if (lane == 0) { r0[wid] = stc; r1[wid] = strl; r2[wid] = cnt; }
    __syncthreads();
    if (wid == 0) {
        stc  = (lane < (TPB / 32)) ? r0[lane] : 0.f;
        strl = (lane < (TPB / 32)) ? r1[lane] : 0.f;
        cnt  = (lane < (TPB / 32)) ? r2[lane] : 0.f;
#pragma unroll
        for (int o = 4; o; o >>= 1) {
            stc  += __shfl_down_sync(m, stc,  o);
            strl += __shfl_down_sync(m, strl, o);
            cnt  += __shfl_down_sync(m, cnt,  o);
        }
        if (lane == 0) {
            atomicAdd(&g_acc[b * 3 + 0], stc);
            atomicAdd(&g_acc[b * 3 + 1], strl);
            atomicAdd(&g_acc[b * 3 + 2], cnt);
        }
    }
}

__global__ void finalize_kernel(float* __restrict__ out, int B) {
    if (threadIdx.x == 0) {
        float t = 0.f;
        for (int b = 0; b < B; b++) {
            float c = g_acc[b * 3 + 2];
            float safe = (c > 0.f) ? c : 1.f;
            t += g_acc[b * 3 + 0] / safe;                 // stc (undivided sum if no pos)
            if (c > 0.f) t += g_acc[b * 3 + 1] / safe;    // str (0 if no pos)
        }
        out[0] = t / (float)B;
    }
}

extern "C" void kernel_launch(void* const* d_in, const int* in_sizes, int n_in,
                              void* d_out, int out_size) {
    const float* prop    = (const float*)d_in[0];  // ss_proposal (B,A,6)
    const float* anchors = (const float*)d_in[1];  // anchors (A,4)
    const float* gt      = (const float*)d_in[2];  // ground_truth (B,K,4)

    const int A = in_sizes[1] / 4;
    const int B = in_sizes[0] / (A * 6);
    const int K = in_sizes[2] / (B * 4);

    zero_acc_kernel<<<1, 32>>>();
    dim3 grid((A + TPB - 1) / TPB, B);
    loss_kernel<<<grid, TPB>>>(prop, anchors, gt, A, K);
    finalize_kernel<<<1, 32>>>((float*)d_out, B);
}